// round 2
// baseline (speedup 1.0000x reference)
#include <cuda_runtime.h>

// out[m,o] = sum_c |x[m,c] - w[c,o]| + b[o]
//          = 2*sum_c max(x[m,c], w[c,o]) - Sx[m] - Sw[o] + b[o]
// Hot loop: FMNMX (alu pipe) x2 + add.rn.f32x2 (fma pipe) x1 per output pair.

constexpr int C    = 64;    // channels (reduction dim)
constexpr int OUTC = 128;   // output channels
constexpr int BM   = 64;    // rows per block
constexpr int BO   = 64;    // output cols per block
constexpr int XS   = 68;    // padded stride for transposed x tile

__global__ __launch_bounds__(256)
void lp1_maxtrick_kernel(const float* __restrict__ x,
                         const float* __restrict__ w,
                         const float* __restrict__ b,
                         float* __restrict__ out)
{
    __shared__ float w_s[C * BO];   // [c][o]
    __shared__ float x_s[C * XS];   // [c][m] transposed, padded
    __shared__ float sx_s[BM];
    __shared__ float beta_s[BO];

    const int tid   = threadIdx.x;
    const int m_blk = blockIdx.x * BM;
    const int o_blk = blockIdx.y * BO;

    // ---- stage w slice [C][BO] ----
    #pragma unroll
    for (int i = 0; i < 4; ++i) {
        int idx = tid + 256 * i;
        int c   = idx >> 4;
        int o4  = idx & 15;
        float4 v = *(const float4*)(w + c * OUTC + o_blk + o4 * 4);
        *(float4*)(&w_s[c * BO + o4 * 4]) = v;
    }

    // ---- stage x tile transposed ----
    #pragma unroll
    for (int i = 0; i < 4; ++i) {
        int idx = tid + 256 * i;
        int m   = idx >> 4;
        int c   = (idx & 15) << 2;
        float4 v = *(const float4*)(x + (size_t)(m_blk + m) * C + c);
        x_s[(c + 0) * XS + m] = v.x;
        x_s[(c + 1) * XS + m] = v.y;
        x_s[(c + 2) * XS + m] = v.z;
        x_s[(c + 3) * XS + m] = v.w;
    }
    __syncthreads();

    // ---- prologue: beta[o] = b[o] - Sw[o]; sx[m] = sum_c x ----
    if (tid < BO) {
        float s = 0.f;
        #pragma unroll
        for (int c = 0; c < C; ++c) s += w_s[c * BO + tid];
        beta_s[tid] = b[o_blk + tid] - s;
    } else if (tid < BO + BM) {
        int m = tid - BO;
        float s = 0.f;
        #pragma unroll
        for (int c = 0; c < C; ++c) s += x_s[c * XS + m];
        sx_s[m] = s;
    }
    __syncthreads();

    // ---- main loop: 4x4 tile, f32x2 packed accumulate ----
    const int o0 = (tid & 15) * 4;
    const int m0 = (tid >> 4) * 4;

    unsigned long long acc[4][2];   // acc[i][k] holds (sum_j=2k, sum_j=2k+1) as f32x2
    #pragma unroll
    for (int i = 0; i < 4; ++i) {
        acc[i][0] = 0ull;
        acc[i][1] = 0ull;
    }

    const float* xp = &x_s[m0];
    const float* wp = &w_s[o0];
    float4 xv = *(const float4*)(xp);
    float4 wv = *(const float4*)(wp);

    #pragma unroll
    for (int c = 0; c < C; ++c) {
        float4 xn, wn;
        if (c + 1 < C) {                 // compile-time guard (full unroll)
            xn = *(const float4*)(xp + (c + 1) * XS);
            wn = *(const float4*)(wp + (c + 1) * BO);
        }
        float xa[4] = {xv.x, xv.y, xv.z, xv.w};
        float wa[4] = {wv.x, wv.y, wv.z, wv.w};
        #pragma unroll
        for (int i = 0; i < 4; ++i) {
            #pragma unroll
            for (int k = 0; k < 2; ++k) {
                float a0 = fmaxf(xa[i], wa[2 * k]);       // FMNMX (alu)
                float a1 = fmaxf(xa[i], wa[2 * k + 1]);   // FMNMX (alu)
                asm("{\n\t"
                    ".reg .b64 t;\n\t"
                    "mov.b64 t, {%1, %2};\n\t"
                    "add.rn.f32x2 %0, %0, t;\n\t"          // packed FADD (fma)
                    "}"
                    : "+l"(acc[i][k]) : "f"(a0), "f"(a1));
            }
        }
        if (c + 1 < C) { xv = xn; wv = wn; }
    }

    // ---- epilogue: out = 2*acc - sx + beta ----
    float bet[4];
    #pragma unroll
    for (int j = 0; j < 4; ++j) bet[j] = beta_s[o0 + j];

    #pragma unroll
    for (int i = 0; i < 4; ++i) {
        float base = -sx_s[m0 + i];
        float s0, s1, s2, s3;
        asm("mov.b64 {%0, %1}, %2;" : "=f"(s0), "=f"(s1) : "l"(acc[i][0]));
        asm("mov.b64 {%0, %1}, %2;" : "=f"(s2), "=f"(s3) : "l"(acc[i][1]));
        float4 r;
        r.x = fmaf(2.f, s0, base + bet[0]);
        r.y = fmaf(2.f, s1, base + bet[1]);
        r.z = fmaf(2.f, s2, base + bet[2]);
        r.w = fmaf(2.f, s3, base + bet[3]);
        *(float4*)(out + (size_t)(m_blk + m0 + i) * OUTC + o_blk + o0) = r;
    }
}

extern "C" void kernel_launch(void* const* d_in, const int* in_sizes, int n_in,
                              void* d_out, int out_size)
{
    const float* x = (const float*)d_in[0];   // [M, 64]
    const float* w = (const float*)d_in[1];   // [64, 128]
    const float* b = (const float*)d_in[2];   // [128]
    float* out = (float*)d_out;               // [M, 128]

    int M = in_sizes[0] / C;                  // 25088
    dim3 grid(M / BM, OUTC / BO);             // (392, 2)
    lp1_maxtrick_kernel<<<grid, 256>>>(x, w, b, out);
}